// round 4
// baseline (speedup 1.0000x reference)
#include <cuda_runtime.h>

#define G     8
#define CIN   64
#define COUT  64
#define KS    7
#define PAD   3
#define H     56
#define W     56
#define B     4

#define TH    8             // output rows per attn block
#define TRW   (TH + KS - 1) // 14 staged rows
#define SP    66            // shared row stride (floats), even + bank stagger

typedef unsigned long long ull;

// scratch (allocation-free rule), interior 56x56 layout
__device__ float g_q[B*COUT*H*W];
__device__ float g_k[B*COUT*H*W];
__device__ float g_v[B*COUT*H*W];

// ---- packed f32x2 helpers (sm_103a) --------------------------------------
__device__ __forceinline__ ull pk(float lo, float hi) {
    ull r; asm("mov.b64 %0, {%1, %2};" : "=l"(r) : "f"(lo), "f"(hi)); return r;
}
__device__ __forceinline__ void upk(float& lo, float& hi, ull p) {
    asm("mov.b64 {%0, %1}, %2;" : "=f"(lo), "=f"(hi) : "l"(p));
}
__device__ __forceinline__ ull fma2(ull a, ull b, ull c) {
    ull r; asm("fma.rn.f32x2 %0, %1, %2, %3;" : "=l"(r) : "l"(a), "l"(b), "l"(c)); return r;
}
__device__ __forceinline__ ull add2(ull a, ull b) {
    ull r; asm("add.rn.f32x2 %0, %1, %2;" : "=l"(r) : "l"(a), "l"(b)); return r;
}
#define EX2F(dst, src) asm("ex2.approx.ftz.f32 %0, %1;" : "=f"(dst) : "f"(src))

// one packed tap: logits = fma2(qq,K,A); exp halves; accumulate packed
__device__ __forceinline__ void tap2(ull qq, ull K, ull A, ull V, ull& S, ull& O) {
    ull L = fma2(qq, K, A);
    float l0, l1; upk(l0, l1, L);
    float e0, e1; EX2F(e0, l0); EX2F(e1, l1);
    ull E = pk(e0, e1);
    S = add2(S, E);
    O = fma2(E, V, O);
}

// ---------------------------------------------------------------------------
// Kernel 1: fused grouped 1x1 conv, 4 outputs/thread, f32x2 math.
// log2(e) folded into wq.
// ---------------------------------------------------------------------------
__global__ __launch_bounds__(256)
void qkv_kernel(const float* __restrict__ x,
                const float* __restrict__ wq,
                const float* __restrict__ wk,
                const float* __restrict__ bk,
                const float* __restrict__ wv,
                const float* __restrict__ bv) {
    const float LOG2E = 1.4426950408889634f;
    int idx = blockIdx.x * 256 + threadIdx.x;          // 200,704 threads exact
    int t = idx / 14;
    int j = idx - t*14;
    int h = t % 56;  t /= 56;
    int c = t % 64;
    int b = t / 64;
    int g = c >> 3;

    const ulonglong2* xp = (const ulonglong2*)x + ((b*CIN + g*8)*H + h)*14 + j;

    float kb = __ldg(&bk[c]);
    float vb = __ldg(&bv[c]);
    ull aq0 = pk(0.f, 0.f), aq1 = aq0;
    ull ak0 = pk(kb, kb),  ak1 = ak0;
    ull av0 = pk(vb, vb),  av1 = av0;

    #pragma unroll
    for (int i = 0; i < 8; i++) {
        ulonglong2 xv = __ldg(xp + i*784);
        float wqi = __ldg(&wq[c*8 + i]) * LOG2E;
        float wki = __ldg(&wk[c*8 + i]);
        float wvi = __ldg(&wv[c*8 + i]);
        ull wq2 = pk(wqi, wqi), wk2 = pk(wki, wki), wv2 = pk(wvi, wvi);
        aq0 = fma2(wq2, xv.x, aq0); aq1 = fma2(wq2, xv.y, aq1);
        ak0 = fma2(wk2, xv.x, ak0); ak1 = fma2(wk2, xv.y, ak1);
        av0 = fma2(wv2, xv.x, av0); av1 = fma2(wv2, xv.y, av1);
    }
    ((ulonglong2*)g_q)[idx] = make_ulonglong2(aq0, aq1);
    ((ulonglong2*)g_k)[idx] = make_ulonglong2(ak0, ak1);
    ((ulonglong2*)g_v)[idx] = make_ulonglong2(av0, av1);
}

// ---------------------------------------------------------------------------
// Kernel 2: windowed softmax attention, 2 adjacent outputs/thread, packed
// f32x2 taps. Block = 8 rows x 28 col-pairs = 224 thr, grid 1792.
//   output0 taps pair as (0,1)(2,3)(4,5) on K0,K1,K2 + scalar tap6 (lo K3)
//   output1 taps pair as (1,2)(3,4)(5,6) on K1,K2,K3 + scalar tap0 (hi K0)
// ---------------------------------------------------------------------------
__device__ __forceinline__ void jy_body(
    const float* ks_, const float* vs_, int rb,
    ull qq0, ull qq1, float q0, float q1,
    ull A00, ull A01, ull A02, float a06,
    float a10, ull A10, ull A11, ull A12,
    ull& sA, ull& oA, ull& sB, ull& oB,
    float& s0, float& o0, float& s1, float& o1)
{
    const ull* kp = (const ull*)(ks_ + rb);
    const ull* vp = (const ull*)(vs_ + rb);
    ull K0 = kp[0], K1 = kp[1], K2 = kp[2], K3 = kp[3];
    ull V0 = vp[0], V1 = vp[1], V2 = vp[2], V3 = vp[3];

    tap2(qq0, K0, A00, V0, sA, oA);
    tap2(qq0, K1, A01, V1, sA, oA);
    tap2(qq0, K2, A02, V2, sA, oA);
    tap2(qq1, K1, A10, V1, sB, oB);
    tap2(qq1, K2, A11, V2, sB, oB);
    tap2(qq1, K3, A12, V3, sB, oB);

    // leftovers: out0 tap6 -> lo(K3), out1 tap0 -> hi(K0)
    float k0l, k0h, k3l, k3h, v0l, v0h, v3l, v3h;
    upk(k0l, k0h, K0); upk(k3l, k3h, K3);
    upk(v0l, v0h, V0); upk(v3l, v3h, V3);
    float l0 = fmaf(q0, k3l, a06);
    float l1 = fmaf(q1, k0h, a10);
    float e0, e1; EX2F(e0, l0); EX2F(e1, l1);
    s0 += e0; o0 = fmaf(e0, v3l, o0);
    s1 += e1; o1 = fmaf(e1, v0h, o1);
}

__global__ __launch_bounds__(224)
void attn_kernel(const float* __restrict__ rel_x,
                 const float* __restrict__ rel_y,
                 const float* __restrict__ bk,
                 const float* __restrict__ bv,
                 float* __restrict__ out) {
    __shared__ __align__(16) float ks_[TRW*SP];
    __shared__ __align__(16) float vs_[TRW*SP];

    int ht = blockIdx.x;   // 0..6
    int c  = blockIdx.y;   // 0..63
    int b  = blockIdx.z;   // 0..3
    int h0 = ht * TH;
    int tid = threadIdx.x;
    int d = c & 7;

    float kb = __ldg(&bk[c]);
    float vb = __ldg(&bv[c]);

    // stage padded 14x62 tile from interior-grid k/v; halo = bias
    int cbase = (b*COUT + c)*H;
    for (int i = tid; i < TRW*64; i += 224) {
        int pr = i >> 6, pc = i & 63;
        int hy = h0 + pr - PAD, wx = pc - PAD;
        bool in = ((unsigned)hy < (unsigned)H) && ((unsigned)wx < (unsigned)W);
        int gi = (cbase + hy)*W + wx;
        int si = pr*SP + pc;
        ks_[si] = in ? g_k[gi] : kb;
        vs_[si] = in ? g_v[gi] : vb;
    }
    __syncthreads();

    int r  = tid / 28;          // local row 0..7
    int wp = tid - r*28;        // col pair 0..27
    int h  = h0 + r;
    int w0 = wp * 2;

    float2 qv = ((const float2*)g_q)[(cbase + h)*28 + wp];  // pre-scaled by log2e
    float q0 = qv.x, q1 = qv.y;
    ull qq0 = pk(q0, q0), qq1 = pk(q1, q1);

    float relv[7];
    #pragma unroll
    for (int jj = 0; jj < 7; jj++)
        relv[jj] = (d < 4) ? __ldg(&rel_x[d*KS + jj]) : __ldg(&rel_y[(d-4)*KS + jj]);

    ull sA = pk(0.f,0.f), oA = sA, sB = sA, oB = sA;
    float s0 = 0.f, o0 = 0.f, s1 = 0.f, o1 = 0.f;

    if (d < 4) {
        // rel constant over jx: a's recomputed per jy (uniform across taps)
        #pragma unroll
        for (int jy = 0; jy < KS; jy++) {
            int rb = (r + jy)*SP + w0;
            float a0 = q0 * relv[jy];
            float a1 = q1 * relv[jy];
            ull A0 = pk(a0, a0), A1 = pk(a1, a1);
            jy_body(ks_, vs_, rb, qq0, qq1, q0, q1,
                    A0, A0, A0, a0, a1, A1, A1, A1,
                    sA, oA, sB, oB, s0, o0, s1, o1);
        }
    } else {
        // rel varies over jx: hoist all a-pairs per thread
        ull A00 = pk(q0*relv[0], q0*relv[1]);
        ull A01 = pk(q0*relv[2], q0*relv[3]);
        ull A02 = pk(q0*relv[4], q0*relv[5]);
        float a06 = q0*relv[6];
        float a10 = q1*relv[0];
        ull A10 = pk(q1*relv[1], q1*relv[2]);
        ull A11 = pk(q1*relv[3], q1*relv[4]);
        ull A12 = pk(q1*relv[5], q1*relv[6]);
        #pragma unroll
        for (int jy = 0; jy < KS; jy++) {
            int rb = (r + jy)*SP + w0;
            jy_body(ks_, vs_, rb, qq0, qq1, q0, q1,
                    A00, A01, A02, a06, a10, A10, A11, A12,
                    sA, oA, sB, oB, s0, o0, s1, o1);
        }
    }

    float sAl, sAh, oAl, oAh, sBl, sBh, oBl, oBh;
    upk(sAl, sAh, sA); upk(oAl, oAh, oA);
    upk(sBl, sBh, sB); upk(oBl, oBh, oB);
    float st0 = sAl + sAh + s0;
    float ot0 = oAl + oAh + o0;
    float st1 = sBl + sBh + s1;
    float ot1 = oBl + oBh + o1;

    float2 res;
    res.x = __fdividef(ot0, st0);
    res.y = __fdividef(ot1, st1);
    *(float2*)&out[(cbase + h)*W + w0] = res;
}

// ---------------------------------------------------------------------------
extern "C" void kernel_launch(void* const* d_in, const int* in_sizes, int n_in,
                              void* d_out, int out_size) {
    const float* x     = (const float*)d_in[0];
    const float* wq    = (const float*)d_in[1];
    const float* wk    = (const float*)d_in[2];
    const float* bk    = (const float*)d_in[3];
    const float* wv    = (const float*)d_in[4];
    const float* bv    = (const float*)d_in[5];
    const float* rel_x = (const float*)d_in[6];
    const float* rel_y = (const float*)d_in[7];
    float* out = (float*)d_out;

    qkv_kernel<<<784, 256>>>(x, wq, wk, bk, wv, bv);

    dim3 grid(H/TH, COUT, B);   // (7, 64, 4) = 1792 blocks
    attn_kernel<<<grid, 224>>>(rel_x, rel_y, bk, bv, out);
}

// round 5
// speedup vs baseline: 1.0137x; 1.0137x over previous
#include <cuda_runtime.h>

#define G     8
#define CIN   64
#define COUT  64
#define KS    7
#define PAD   3
#define H     56
#define W     56
#define B     4

#define TH    8             // output rows per attn block
#define TRW   (TH + KS - 1) // 14 staged rows
#define SP    66            // shared row stride (floats), even + bank stagger

// scratch (allocation-free rule), interior 56x56 layout
__device__ float g_q[B*COUT*H*W];
__device__ float g_k[B*COUT*H*W];
__device__ float g_v[B*COUT*H*W];

#define EX2F(dst, src) asm("ex2.approx.ftz.f32 %0, %1;" : "=f"(dst) : "f"(src))

// ---------------------------------------------------------------------------
// Kernel 1: fused grouped 1x1 conv, 4 outputs/thread (float4).
// log2(e) folded into wq.
// ---------------------------------------------------------------------------
__global__ __launch_bounds__(256)
void qkv_kernel(const float* __restrict__ x,
                const float* __restrict__ wq,
                const float* __restrict__ wk,
                const float* __restrict__ bk,
                const float* __restrict__ wv,
                const float* __restrict__ bv) {
    const float LOG2E = 1.4426950408889634f;
    int idx = blockIdx.x * 256 + threadIdx.x;          // 200,704 threads exact
    int t = idx / 14;
    int j = idx - t*14;
    int h = t % 56;  t /= 56;
    int c = t % 64;
    int b = t / 64;
    int g = c >> 3;

    const float4* xp = (const float4*)x + ((b*CIN + g*8)*H + h)*14 + j;

    float kb = __ldg(&bk[c]);
    float vb = __ldg(&bv[c]);
    float4 aq = make_float4(0.f, 0.f, 0.f, 0.f);
    float4 ak = make_float4(kb, kb, kb, kb);
    float4 av = make_float4(vb, vb, vb, vb);

    #pragma unroll
    for (int i = 0; i < 8; i++) {
        float4 xv  = __ldg(xp + i*784);                 // 784 = H*W/4
        float wqi  = __ldg(&wq[c*8 + i]) * LOG2E;
        float wki  = __ldg(&wk[c*8 + i]);
        float wvi  = __ldg(&wv[c*8 + i]);
        aq.x = fmaf(wqi, xv.x, aq.x); aq.y = fmaf(wqi, xv.y, aq.y);
        aq.z = fmaf(wqi, xv.z, aq.z); aq.w = fmaf(wqi, xv.w, aq.w);
        ak.x = fmaf(wki, xv.x, ak.x); ak.y = fmaf(wki, xv.y, ak.y);
        ak.z = fmaf(wki, xv.z, ak.z); ak.w = fmaf(wki, xv.w, ak.w);
        av.x = fmaf(wvi, xv.x, av.x); av.y = fmaf(wvi, xv.y, av.y);
        av.z = fmaf(wvi, xv.z, av.z); av.w = fmaf(wvi, xv.w, av.w);
    }
    ((float4*)g_q)[idx] = aq;
    ((float4*)g_k)[idx] = ak;
    ((float4*)g_v)[idx] = av;
}

// ---------------------------------------------------------------------------
// Kernel 2: windowed softmax attention, 2 adjacent outputs/thread.
// Block = 8 rows x 28 col-pairs = 224 threads, grid 1792.
// d<4: rel const over jx -> hoist a = q*rel[jy] per jy   (4 ops/tap)
// d>=4: rel varies over jx -> a = q*rel[jx] inline       (5 ops/tap, 0 arrays)
// Register-pinned via launch_bounds(224, 8) for >=8 blocks/SM.
// ---------------------------------------------------------------------------
__global__ __launch_bounds__(224, 8)
void attn_kernel(const float* __restrict__ rel_x,
                 const float* __restrict__ rel_y,
                 const float* __restrict__ bk,
                 const float* __restrict__ bv,
                 float* __restrict__ out) {
    __shared__ __align__(16) float ks_[TRW*SP];
    __shared__ __align__(16) float vs_[TRW*SP];

    int ht = blockIdx.x;   // 0..6
    int c  = blockIdx.y;   // 0..63
    int b  = blockIdx.z;   // 0..3
    int h0 = ht * TH;
    int tid = threadIdx.x;
    int d = c & 7;

    float kb = __ldg(&bk[c]);
    float vb = __ldg(&bv[c]);

    // stage padded 14x62 tile from interior-grid k/v; halo = bias
    int cbase = (b*COUT + c)*H;
    for (int i = tid; i < TRW*64; i += 224) {
        int pr = i >> 6, pc = i & 63;
        int hy = h0 + pr - PAD, wx = pc - PAD;
        bool in = ((unsigned)hy < (unsigned)H) && ((unsigned)wx < (unsigned)W);
        int gi = (cbase + hy)*W + wx;
        int si = pr*SP + pc;
        ks_[si] = in ? g_k[gi] : kb;
        vs_[si] = in ? g_v[gi] : vb;
    }
    __syncthreads();

    int r  = tid / 28;          // local row 0..7
    int wp = tid - r*28;        // col pair 0..27
    int h  = h0 + r;
    int w0 = wp * 2;

    float2 qv = ((const float2*)g_q)[(cbase + h)*28 + wp];  // pre-scaled by log2e
    float q0 = qv.x, q1 = qv.y;

    float relv[7];
    #pragma unroll
    for (int jj = 0; jj < 7; jj++)
        relv[jj] = (d < 4) ? __ldg(&rel_x[d*KS + jj]) : __ldg(&rel_y[(d-4)*KS + jj]);

    float s0 = 0.f, s1 = 0.f, o0 = 0.f, o1 = 0.f;

    if (d < 4) {
        #pragma unroll
        for (int jy = 0; jy < KS; jy++) {
            const float2* kp = (const float2*)(ks_ + (r + jy)*SP + w0);
            const float2* vp = (const float2*)(vs_ + (r + jy)*SP + w0);
            float2 ka = kp[0], kc = kp[1], ke = kp[2], kg = kp[3];
            float2 va = vp[0], vc = vp[1], ve = vp[2], vg = vp[3];
            float a0 = q0 * relv[jy];
            float a1 = q1 * relv[jy];
            float e;
            // out0 taps 0..6 over {ka.x,ka.y,kc.x,kc.y,ke.x,ke.y,kg.x}
            EX2F(e, fmaf(q0, ka.x, a0)); s0 += e; o0 = fmaf(e, va.x, o0);
            EX2F(e, fmaf(q0, ka.y, a0)); s0 += e; o0 = fmaf(e, va.y, o0);
            EX2F(e, fmaf(q0, kc.x, a0)); s0 += e; o0 = fmaf(e, vc.x, o0);
            EX2F(e, fmaf(q0, kc.y, a0)); s0 += e; o0 = fmaf(e, vc.y, o0);
            EX2F(e, fmaf(q0, ke.x, a0)); s0 += e; o0 = fmaf(e, ve.x, o0);
            EX2F(e, fmaf(q0, ke.y, a0)); s0 += e; o0 = fmaf(e, ve.y, o0);
            EX2F(e, fmaf(q0, kg.x, a0)); s0 += e; o0 = fmaf(e, vg.x, o0);
            // out1 taps over {ka.y,kc.x,kc.y,ke.x,ke.y,kg.x,kg.y}
            EX2F(e, fmaf(q1, ka.y, a1)); s1 += e; o1 = fmaf(e, va.y, o1);
            EX2F(e, fmaf(q1, kc.x, a1)); s1 += e; o1 = fmaf(e, vc.x, o1);
            EX2F(e, fmaf(q1, kc.y, a1)); s1 += e; o1 = fmaf(e, vc.y, o1);
            EX2F(e, fmaf(q1, ke.x, a1)); s1 += e; o1 = fmaf(e, ve.x, o1);
            EX2F(e, fmaf(q1, ke.y, a1)); s1 += e; o1 = fmaf(e, ve.y, o1);
            EX2F(e, fmaf(q1, kg.x, a1)); s1 += e; o1 = fmaf(e, vg.x, o1);
            EX2F(e, fmaf(q1, kg.y, a1)); s1 += e; o1 = fmaf(e, vg.y, o1);
        }
    } else {
        #pragma unroll
        for (int jy = 0; jy < KS; jy++) {
            const float2* kp = (const float2*)(ks_ + (r + jy)*SP + w0);
            const float2* vp = (const float2*)(vs_ + (r + jy)*SP + w0);
            float2 ka = kp[0], kc = kp[1], ke = kp[2], kg = kp[3];
            float2 va = vp[0], vc = vp[1], ve = vp[2], vg = vp[3];
            float e;
            EX2F(e, fmaf(q0, ka.x, q0*relv[0])); s0 += e; o0 = fmaf(e, va.x, o0);
            EX2F(e, fmaf(q0, ka.y, q0*relv[1])); s0 += e; o0 = fmaf(e, va.y, o0);
            EX2F(e, fmaf(q0, kc.x, q0*relv[2])); s0 += e; o0 = fmaf(e, vc.x, o0);
            EX2F(e, fmaf(q0, kc.y, q0*relv[3])); s0 += e; o0 = fmaf(e, vc.y, o0);
            EX2F(e, fmaf(q0, ke.x, q0*relv[4])); s0 += e; o0 = fmaf(e, ve.x, o0);
            EX2F(e, fmaf(q0, ke.y, q0*relv[5])); s0 += e; o0 = fmaf(e, ve.y, o0);
            EX2F(e, fmaf(q0, kg.x, q0*relv[6])); s0 += e; o0 = fmaf(e, vg.x, o0);
            EX2F(e, fmaf(q1, ka.y, q1*relv[0])); s1 += e; o1 = fmaf(e, va.y, o1);
            EX2F(e, fmaf(q1, kc.x, q1*relv[1])); s1 += e; o1 = fmaf(e, vc.x, o1);
            EX2F(e, fmaf(q1, kc.y, q1*relv[2])); s1 += e; o1 = fmaf(e, vc.y, o1);
            EX2F(e, fmaf(q1, ke.x, q1*relv[3])); s1 += e; o1 = fmaf(e, ve.x, o1);
            EX2F(e, fmaf(q1, ke.y, q1*relv[4])); s1 += e; o1 = fmaf(e, ve.y, o1);
            EX2F(e, fmaf(q1, kg.x, q1*relv[5])); s1 += e; o1 = fmaf(e, vg.x, o1);
            EX2F(e, fmaf(q1, kg.y, q1*relv[6])); s1 += e; o1 = fmaf(e, vg.y, o1);
        }
    }

    float2 res;
    res.x = __fdividef(o0, s0);
    res.y = __fdividef(o1, s1);
    *(float2*)&out[(cbase + h)*W + w0] = res;
}

// ---------------------------------------------------------------------------
extern "C" void kernel_launch(void* const* d_in, const int* in_sizes, int n_in,
                              void* d_out, int out_size) {
    const float* x     = (const float*)d_in[0];
    const float* wq    = (const float*)d_in[1];
    const float* wk    = (const float*)d_in[2];
    const float* bk    = (const float*)d_in[3];
    const float* wv    = (const float*)d_in[4];
    const float* bv    = (const float*)d_in[5];
    const float* rel_x = (const float*)d_in[6];
    const float* rel_y = (const float*)d_in[7];
    float* out = (float*)d_out;

    qkv_kernel<<<784, 256>>>(x, wq, wk, bk, wv, bv);

    dim3 grid(H/TH, COUT, B);   // (7, 64, 4) = 1792 blocks
    attn_kernel<<<grid, 224>>>(rel_x, rel_y, bk, bv, out);
}